// round 4
// baseline (speedup 1.0000x reference)
#include <cuda_runtime.h>
#include <cstdint>
#include <cstddef>
#include <math.h>

#define NBLK 128
#define NTHR 256

// ------------------------- device scratch (static, no allocs) -------------------------
__device__ float    g_EW[4096u * 1024u];        // 16 MB: E@W_ih1[:, :256]^T + b_ih1 + b_hh1
__device__ float    g_AllT[256u * 256u * 64u];  // 16 MB: [t][c][b], c<128 h2, c>=128 ctx
__device__ float    g_S1[2][384 * 64];          // lstm1 input state: rows 0..127 ctx, 128..383 h1
__device__ float    g_S2[2][384 * 64];          // lstm2 input state: rows 0..255 h1, 256..383 h2
__device__ float    g_c1[256 * 64];
__device__ float    g_c2[128 * 64];
__device__ unsigned g_flags[NBLK * 8];

__device__ __forceinline__ float sigm(float x) { return 1.0f / (1.0f + expf(-x)); }

// CG-style grid barrier: fence + per-block flag, thread i polls block i's flag.
__device__ __forceinline__ void gbar(unsigned target) {
    __syncthreads();
    if (threadIdx.x == 0) {
        __threadfence();
        atomicExch(&g_flags[blockIdx.x * 8], target);
    }
    if (threadIdx.x < NBLK) {
        volatile unsigned* f = &g_flags[threadIdx.x * 8];
        while (*f < target) { }
        __threadfence();
    }
    __syncthreads();
}

// ------------------------- kernel 0: zero recurrent state -------------------------
__global__ void prep_k() {
    int i0 = blockIdx.x * blockDim.x + threadIdx.x;
    int st = gridDim.x * blockDim.x;
    for (int i = i0; i < 384 * 64; i += st) { g_S1[0][i] = 0.f; g_S2[0][i] = 0.f; }
    for (int i = i0; i < 256 * 64; i += st) g_c1[i] = 0.f;
    for (int i = i0; i < 128 * 64; i += st) g_c2[i] = 0.f;
    for (int i = i0; i < NBLK * 8; i += st) g_flags[i] = 0u;
}

// ------------------------- kernel 1: EW[v][c] = E[v,:] . W_ih1[c, :256] + bias -------------------------
__global__ void __launch_bounds__(256) ew_k(const float* __restrict__ E,
                                            const float* __restrict__ W_ih1,
                                            const float* __restrict__ b_ih1,
                                            const float* __restrict__ b_hh1) {
    __shared__ __align__(16) float sA[16][68];   // [k][v]
    __shared__ __align__(16) float sB[16][68];   // [k][c]
    const int c0 = blockIdx.x * 64, v0 = blockIdx.y * 64;
    const int tid = threadIdx.x;
    const int lw = tid >> 2, kq = tid & 3;
    const int cx = tid & 15, vxx = tid >> 4;
    float4 acc[4];
    acc[0] = acc[1] = acc[2] = acc[3] = make_float4(0, 0, 0, 0);
    for (int k0 = 0; k0 < 256; k0 += 16) {
        float4 av = *(const float4*)(E + (size_t)(v0 + lw) * 256 + k0 + kq * 4);
        float4 bv = *(const float4*)(W_ih1 + (size_t)(c0 + lw) * 384 + k0 + kq * 4);
        __syncthreads();
        sA[kq * 4 + 0][lw] = av.x; sA[kq * 4 + 1][lw] = av.y;
        sA[kq * 4 + 2][lw] = av.z; sA[kq * 4 + 3][lw] = av.w;
        sB[kq * 4 + 0][lw] = bv.x; sB[kq * 4 + 1][lw] = bv.y;
        sB[kq * 4 + 2][lw] = bv.z; sB[kq * 4 + 3][lw] = bv.w;
        __syncthreads();
#pragma unroll
        for (int k = 0; k < 16; k++) {
            float4 cv = *(const float4*)&sB[k][cx * 4];
            float4 vv = *(const float4*)&sA[k][vxx * 4];
            float vs[4] = {vv.x, vv.y, vv.z, vv.w};
#pragma unroll
            for (int vi = 0; vi < 4; vi++) {
                acc[vi].x = fmaf(vs[vi], cv.x, acc[vi].x);
                acc[vi].y = fmaf(vs[vi], cv.y, acc[vi].y);
                acc[vi].z = fmaf(vs[vi], cv.z, acc[vi].z);
                acc[vi].w = fmaf(vs[vi], cv.w, acc[vi].w);
            }
        }
    }
    float4 bi = *(const float4*)(b_ih1 + c0 + cx * 4);
    float4 bh = *(const float4*)(b_hh1 + c0 + cx * 4);
    float4 bias = make_float4(bi.x + bh.x, bi.y + bh.y, bi.z + bh.z, bi.w + bh.w);
#pragma unroll
    for (int vi = 0; vi < 4; vi++) {
        float4 r = make_float4(acc[vi].x + bias.x, acc[vi].y + bias.y,
                               acc[vi].z + bias.z, acc[vi].w + bias.w);
        *(float4*)(g_EW + (size_t)(v0 + vxx * 4 + vi) * 1024 + c0 + cx * 4) = r;
    }
}

// ------------------------- kernel 2: persistent recurrence -------------------------
__global__ void __launch_bounds__(NTHR, 1) recur_k(
    const float* __restrict__ key, const float* __restrict__ values,
    const int* __restrict__ text,
    const float* __restrict__ W_ih1, const float* __restrict__ W_hh1,
    const float* __restrict__ W_ih2, const float* __restrict__ W_hh2,
    const float* __restrict__ b_ih2, const float* __restrict__ b_hh2) {
    __shared__ __align__(16) float sW1[8][384];  // [q*2+jl][k]: k<128 ctx-w, else hh-w
    __shared__ __align__(16) float sW2[4][384];  // [q][k]: k<256 ih(h1), else hh(h2)
    __shared__ float sP[4][8][64];
    __shared__ float sG[8][64];
    __shared__ float sB2[4];
    __shared__ float sH2v[128];
    __shared__ float sEn[512];
    __shared__ float sRed[256];

    const int tid = threadIdx.x;
    const int bid = blockIdx.x;
    const int b = tid & 63, ks = tid >> 6;
    const int k0 = ks * 96;

    for (int i = tid; i < 8 * 384; i += NTHR) {
        int a = i / 384, k = i % 384;
        int c = (a >> 1) * 256 + bid * 2 + (a & 1);
        sW1[a][k] = (k < 128) ? W_ih1[(size_t)c * 384 + 256 + k]
                              : W_hh1[(size_t)c * 256 + (k - 128)];
    }
    for (int i = tid; i < 4 * 384; i += NTHR) {
        int q = i / 384, k = i % 384;
        int c2 = q * 128 + bid;
        sW2[q][k] = (k < 256) ? W_ih2[(size_t)c2 * 256 + k]
                              : W_hh2[(size_t)c2 * 128 + (k - 256)];
    }
    if (tid < 4) sB2[tid] = b_ih2[tid * 128 + bid] + b_hh2[tid * 128 + bid];
    __syncthreads();

    unsigned nb = 0;
    for (int t = 0; t < 256; ++t) {
        const int rd = t & 1, wr = rd ^ 1;
        // ---------- P1: lstm1 gates + cell ----------
        {
            const float* S = g_S1[rd] + b;
            float acc[8];
#pragma unroll
            for (int a = 0; a < 8; a++) acc[a] = 0.f;
#pragma unroll
            for (int kk = 0; kk < 96; kk += 4) {
                int k = k0 + kk;
                float s0 = __ldcg(S + (k + 0) * 64);
                float s1 = __ldcg(S + (k + 1) * 64);
                float s2 = __ldcg(S + (k + 2) * 64);
                float s3 = __ldcg(S + (k + 3) * 64);
#pragma unroll
                for (int a = 0; a < 8; a++) {
                    float4 w = *(const float4*)&sW1[a][k];
                    acc[a] = fmaf(w.x, s0, fmaf(w.y, s1, fmaf(w.z, s2, fmaf(w.w, s3, acc[a]))));
                }
            }
#pragma unroll
            for (int a = 0; a < 8; a++) sP[ks][a][b] = acc[a];
        }
        __syncthreads();
#pragma unroll
        for (int s = 0; s < 2; s++) {
            int o = tid + s * 256;
            int a = o >> 6, b2 = o & 63;
            int c = (a >> 1) * 256 + bid * 2 + (a & 1);
            int row = text[b2 * 256 + t] & 4095;
            sG[a][b2] = sP[0][a][b2] + sP[1][a][b2] + sP[2][a][b2] + sP[3][a][b2]
                      + g_EW[(size_t)row * 1024 + c];
        }
        __syncthreads();
        if (tid < 128) {
            int jl = tid >> 6, b2 = tid & 63;
            int j = bid * 2 + jl;
            float gi = sG[0 + jl][b2], gf = sG[2 + jl][b2];
            float gg = sG[4 + jl][b2], go = sG[6 + jl][b2];
            float cn = sigm(gf) * g_c1[j * 64 + b2] + sigm(gi) * tanhf(gg);
            float hn = sigm(go) * tanhf(cn);
            g_c1[j * 64 + b2] = cn;
            g_S1[wr][(128 + j) * 64 + b2] = hn;  // h1(t) for P1(t+1)
            g_S2[rd][j * 64 + b2] = hn;          // h1(t) for P2(t)
        }
        gbar(++nb);
        // ---------- P2: lstm2 gates + cell ----------
        {
            const float* S = g_S2[rd] + b;
            float acc[4] = {0.f, 0.f, 0.f, 0.f};
#pragma unroll
            for (int kk = 0; kk < 96; kk += 4) {
                int k = k0 + kk;
                float s0 = __ldcg(S + (k + 0) * 64);
                float s1 = __ldcg(S + (k + 1) * 64);
                float s2 = __ldcg(S + (k + 2) * 64);
                float s3 = __ldcg(S + (k + 3) * 64);
#pragma unroll
                for (int q = 0; q < 4; q++) {
                    float4 w = *(const float4*)&sW2[q][k];
                    acc[q] = fmaf(w.x, s0, fmaf(w.y, s1, fmaf(w.z, s2, fmaf(w.w, s3, acc[q]))));
                }
            }
#pragma unroll
            for (int q = 0; q < 4; q++) sP[ks][q][b] = acc[q];
        }
        __syncthreads();
        {
            int q = tid >> 6, b2 = tid & 63;
            sG[q][b2] = sP[0][q][b2] + sP[1][q][b2] + sP[2][q][b2] + sP[3][q][b2] + sB2[q];
        }
        __syncthreads();
        if (tid < 64) {
            int b2 = tid;
            float gi = sG[0][b2], gf = sG[1][b2], gg = sG[2][b2], go = sG[3][b2];
            float cn = sigm(gf) * g_c2[bid * 64 + b2] + sigm(gi) * tanhf(gg);
            float hn = sigm(go) * tanhf(cn);
            g_c2[bid * 64 + b2] = cn;
            g_S2[wr][(256 + bid) * 64 + b2] = hn;               // h2(t) for P2(t+1)/P3(t)
            g_AllT[(size_t)t * 16384 + bid * 64 + b2] = hn;     // h2 for logits
        }
        gbar(++nb);
        // ---------- P3: attention (blocks 0..63, one batch row each) ----------
        if (bid < 64) {
            const int b3 = bid;
            if (tid < 128) sH2v[tid] = __ldcg(&g_S2[wr][(256 + tid) * 64 + b3]);
            __syncthreads();
#pragma unroll
            for (int s = 0; s < 2; s++) {
                int tp = tid + s * 256;
                const float4* kp = (const float4*)(key + ((size_t)b3 * 512 + tp) * 128);
                float e = 0.f;
#pragma unroll
                for (int i = 0; i < 32; i++) {
                    float4 kv = kp[i];
                    e = fmaf(kv.x, sH2v[4 * i + 0], fmaf(kv.y, sH2v[4 * i + 1],
                        fmaf(kv.z, sH2v[4 * i + 2], fmaf(kv.w, sH2v[4 * i + 3], e))));
                }
                sEn[tp] = e;
            }
            __syncthreads();
            sRed[tid] = fmaxf(sEn[tid], sEn[tid + 256]);
            __syncthreads();
            for (int off = 128; off > 0; off >>= 1) {
                if (tid < off) sRed[tid] = fmaxf(sRed[tid], sRed[tid + off]);
                __syncthreads();
            }
            float mx = sRed[0];
            __syncthreads();
            float e0 = expf(sEn[tid] - mx), e1 = expf(sEn[tid + 256] - mx);
            sEn[tid] = e0; sEn[tid + 256] = e1;
            sRed[tid] = e0 + e1;
            __syncthreads();
            for (int off = 128; off > 0; off >>= 1) {
                if (tid < off) sRed[tid] += sRed[tid + off];
                __syncthreads();
            }
            float inv = 1.f / sRed[0];
            int v = tid & 127, hf = tid >> 7;
            const float* vb = values + (size_t)b3 * 512 * 128 + v;
            float acc = 0.f;
#pragma unroll 8
            for (int tp = hf * 256; tp < hf * 256 + 256; ++tp)
                acc = fmaf(sEn[tp], vb[(size_t)tp * 128], acc);
            acc *= inv;
            __syncthreads();
            sRed[hf * 128 + v] = acc;
            __syncthreads();
            if (tid < 128) {
                float cv = sRed[tid] + sRed[128 + tid];
                g_S1[wr][tid * 64 + b3] = cv;                        // ctx(t) for P1(t+1)
                g_AllT[(size_t)t * 16384 + (128 + tid) * 64 + b3] = cv;
            }
        }
        gbar(++nb);
    }
}

// ------------------------- kernel 3: logits = AllT^T @ E^T + b_out -------------------------
__global__ void __launch_bounds__(256) logits_k(const float* __restrict__ E,
                                                const float* __restrict__ b_out,
                                                float* __restrict__ out) {
    __shared__ __align__(16) float sX[16][68];   // [c][b]
    __shared__ __align__(16) float sEt[16][68];  // [c][v]
    const int v0 = blockIdx.x * 64;
    const int t = blockIdx.y;
    const int tid = threadIdx.x;
    const int cl = tid >> 4, bq = tid & 15;   // sX loader
    const int vl = tid >> 2, cq = tid & 3;    // sEt loader
    const int vx = tid & 15, bx = tid >> 4;   // compute
    float4 acc[4];
    acc[0] = acc[1] = acc[2] = acc[3] = make_float4(0, 0, 0, 0);
    for (int c0 = 0; c0 < 256; c0 += 16) {
        float4 xv = *(const float4*)(g_AllT + (size_t)t * 16384 + (size_t)(c0 + cl) * 64 + bq * 4);
        float4 ev = *(const float4*)(E + (size_t)(v0 + vl) * 256 + c0 + cq * 4);
        __syncthreads();
        *(float4*)&sX[cl][bq * 4] = xv;
        sEt[cq * 4 + 0][vl] = ev.x; sEt[cq * 4 + 1][vl] = ev.y;
        sEt[cq * 4 + 2][vl] = ev.z; sEt[cq * 4 + 3][vl] = ev.w;
        __syncthreads();
#pragma unroll
        for (int k = 0; k < 16; k++) {
            float4 e4 = *(const float4*)&sEt[k][vx * 4];
            float4 x4 = *(const float4*)&sX[k][bx * 4];
            float xs[4] = {x4.x, x4.y, x4.z, x4.w};
#pragma unroll
            for (int bj = 0; bj < 4; bj++) {
                acc[bj].x = fmaf(xs[bj], e4.x, acc[bj].x);
                acc[bj].y = fmaf(xs[bj], e4.y, acc[bj].y);
                acc[bj].z = fmaf(xs[bj], e4.z, acc[bj].z);
                acc[bj].w = fmaf(xs[bj], e4.w, acc[bj].w);
            }
        }
    }
    float4 bo = *(const float4*)(b_out + v0 + vx * 4);
#pragma unroll
    for (int bj = 0; bj < 4; bj++) {
        int bb = bx * 4 + bj;
        float4 r = make_float4(acc[bj].x + bo.x, acc[bj].y + bo.y,
                               acc[bj].z + bo.z, acc[bj].w + bo.w);
        *(float4*)(out + ((size_t)bb * 256 + t) * 4096 + v0 + vx * 4) = r;
    }
}

// ------------------------- launch -------------------------
extern "C" void kernel_launch(void* const* d_in, const int* in_sizes, int n_in,
                              void* d_out, int out_size) {
    const float* key    = (const float*)d_in[0];
    const float* values = (const float*)d_in[1];
    const int*   text   = (const int*)d_in[3];
    const float* E      = (const float*)d_in[4];
    const float* W_ih1  = (const float*)d_in[5];
    const float* W_hh1  = (const float*)d_in[6];
    const float* b_ih1  = (const float*)d_in[7];
    const float* b_hh1  = (const float*)d_in[8];
    const float* W_ih2  = (const float*)d_in[9];
    const float* W_hh2  = (const float*)d_in[10];
    const float* b_ih2  = (const float*)d_in[11];
    const float* b_hh2  = (const float*)d_in[12];
    const float* b_out  = (const float*)d_in[13];
    float*       out    = (float*)d_out;

    prep_k<<<128, 256>>>();
    ew_k<<<dim3(16, 64), 256>>>(E, W_ih1, b_ih1, b_hh1);
    recur_k<<<NBLK, NTHR>>>(key, values, text, W_ih1, W_hh1, W_ih2, W_hh2, b_ih2, b_hh2);
    logits_k<<<dim3(64, 256), 256>>>(E, b_out, out);
}

// round 5
// speedup vs baseline: 1.6337x; 1.6337x over previous
#include <cuda_runtime.h>
#include <cstdint>
#include <cstddef>
#include <math.h>

#define NBLK 128
#define NTHR 512

// ------------------------- device scratch (static, no allocs) -------------------------
__device__ float    g_EW[4096u * 1024u];        // [row][c]: E@W_ih1[:, :256]^T + b_ih1 + b_hh1
__device__ float    g_AllT[256u * 256u * 64u];  // [t][c][b], c<128 h2, c>=128 ctx
// state, k-major packed in float4 groups: idx(k,b) = (k>>2)*256 + b*4 + (k&3)
__device__ float    g_S1v[2][96 * 256];         // lstm1 input: k<128 ctx, k in [128,384) h1
__device__ float    g_S2v[2][96 * 256];         // lstm2 input: k<256 h1, k in [256,384) h2
__device__ float    g_c1[256 * 64];
__device__ float    g_c2[128 * 64];
__device__ unsigned g_arrive;
__device__ unsigned g_release;

__device__ __forceinline__ float sigm(float x) { return 1.0f / (1.0f + expf(-x)); }

// centralized grid barrier: thread0 arrives on a monotonic counter; last arriver
// release-stores the epoch; all other thread0s acquire-poll one word.
__device__ __forceinline__ void gbar(unsigned epoch) {
    __syncthreads();
    if (threadIdx.x == 0) {
        __threadfence();
        unsigned prev = atomicAdd(&g_arrive, 1u);
        if (prev == epoch * NBLK - 1u) {
            asm volatile("st.release.gpu.u32 [%0], %1;" :: "l"(&g_release), "r"(epoch) : "memory");
        } else {
            unsigned v;
            do {
                asm volatile("ld.acquire.gpu.u32 %0, [%1];" : "=r"(v) : "l"(&g_release) : "memory");
            } while (v < epoch);
        }
    }
    __syncthreads();
}

// ------------------------- kernel 0: zero recurrent state -------------------------
__global__ void prep_k() {
    int i0 = blockIdx.x * blockDim.x + threadIdx.x;
    int st = gridDim.x * blockDim.x;
    for (int i = i0; i < 96 * 256; i += st) { g_S1v[0][i] = 0.f; g_S2v[0][i] = 0.f; }
    for (int i = i0; i < 256 * 64; i += st) g_c1[i] = 0.f;
    for (int i = i0; i < 128 * 64; i += st) g_c2[i] = 0.f;
    if (i0 == 0) { g_arrive = 0u; g_release = 0u; }
}

// ------------------------- kernel 1: EW[v][c] = E[v,:] . W_ih1[c, :256] + bias -------------------------
__global__ void __launch_bounds__(256) ew_k(const float* __restrict__ E,
                                            const float* __restrict__ W_ih1,
                                            const float* __restrict__ b_ih1,
                                            const float* __restrict__ b_hh1) {
    __shared__ __align__(16) float sA[16][68];   // [k][v]
    __shared__ __align__(16) float sB[16][68];   // [k][c]
    const int c0 = blockIdx.x * 64, v0 = blockIdx.y * 64;
    const int tid = threadIdx.x;
    const int lw = tid >> 2, kq = tid & 3;
    const int cx = tid & 15, vxx = tid >> 4;
    float4 acc[4];
    acc[0] = acc[1] = acc[2] = acc[3] = make_float4(0, 0, 0, 0);
    for (int k0 = 0; k0 < 256; k0 += 16) {
        float4 av = *(const float4*)(E + (size_t)(v0 + lw) * 256 + k0 + kq * 4);
        float4 bv = *(const float4*)(W_ih1 + (size_t)(c0 + lw) * 384 + k0 + kq * 4);
        __syncthreads();
        sA[kq * 4 + 0][lw] = av.x; sA[kq * 4 + 1][lw] = av.y;
        sA[kq * 4 + 2][lw] = av.z; sA[kq * 4 + 3][lw] = av.w;
        sB[kq * 4 + 0][lw] = bv.x; sB[kq * 4 + 1][lw] = bv.y;
        sB[kq * 4 + 2][lw] = bv.z; sB[kq * 4 + 3][lw] = bv.w;
        __syncthreads();
#pragma unroll
        for (int k = 0; k < 16; k++) {
            float4 cv = *(const float4*)&sB[k][cx * 4];
            float4 vv = *(const float4*)&sA[k][vxx * 4];
            float vs[4] = {vv.x, vv.y, vv.z, vv.w};
#pragma unroll
            for (int vi = 0; vi < 4; vi++) {
                acc[vi].x = fmaf(vs[vi], cv.x, acc[vi].x);
                acc[vi].y = fmaf(vs[vi], cv.y, acc[vi].y);
                acc[vi].z = fmaf(vs[vi], cv.z, acc[vi].z);
                acc[vi].w = fmaf(vs[vi], cv.w, acc[vi].w);
            }
        }
    }
    float4 bi = *(const float4*)(b_ih1 + c0 + cx * 4);
    float4 bh = *(const float4*)(b_hh1 + c0 + cx * 4);
    float4 bias = make_float4(bi.x + bh.x, bi.y + bh.y, bi.z + bh.z, bi.w + bh.w);
#pragma unroll
    for (int vi = 0; vi < 4; vi++) {
        float4 r = make_float4(acc[vi].x + bias.x, acc[vi].y + bias.y,
                               acc[vi].z + bias.z, acc[vi].w + bias.w);
        *(float4*)(g_EW + (size_t)(v0 + vxx * 4 + vi) * 1024 + c0 + cx * 4) = r;
    }
}

// ------------------------- kernel 2: persistent recurrence -------------------------
__global__ void __launch_bounds__(NTHR, 1) recur_k(
    const float* __restrict__ key, const float* __restrict__ values,
    const int* __restrict__ text,
    const float* __restrict__ W_ih1, const float* __restrict__ W_hh1,
    const float* __restrict__ W_ih2, const float* __restrict__ W_hh2,
    const float* __restrict__ b_ih2, const float* __restrict__ b_hh2) {
    __shared__ __align__(16) float sW1v[384 * 8];   // [k][a], a = gate*2 + jl
    __shared__ __align__(16) float sW2v[384 * 4];   // [k][q], q = gate
    __shared__ __align__(16) float sP[8 * 8 * 64];  // [ks][a][b]
    __shared__ float sG[8 * 64];
    __shared__ float sB2[4];
    __shared__ __align__(16) float sH2f[128];
    __shared__ float sEn[512];
    __shared__ float sRed[32];
    __shared__ __align__(16) float sVal[16 * 128];

    const int tid = threadIdx.x;
    const int bid = blockIdx.x;
    const int b = tid & 63, ks = tid >> 6;   // 8 k-splits x 64 batch
    const int lane = tid & 31, wrp = tid >> 5;

    // weight staging (k-major)
    for (int i = tid; i < 384 * 8; i += NTHR) {
        int k = i >> 3, a = i & 7;
        int c = (a >> 1) * 256 + bid * 2 + (a & 1);
        sW1v[i] = (k < 128) ? W_ih1[(size_t)c * 384 + 256 + k]
                            : W_hh1[(size_t)c * 256 + (k - 128)];
    }
    for (int i = tid; i < 384 * 4; i += NTHR) {
        int k = i >> 2, q = i & 3;
        int c2 = q * 128 + bid;
        sW2v[i] = (k < 256) ? W_ih2[(size_t)c2 * 256 + k]
                            : W_hh2[(size_t)c2 * 128 + (k - 256)];
    }
    if (tid < 4) sB2[tid] = b_ih2[tid * 128 + bid] + b_hh2[tid * 128 + bid];
    __syncthreads();

    unsigned ep = 0;
    for (int t = 0; t < 256; ++t) {
        const int rd = t & 1, wr = rd ^ 1;
        // ---------- P1: lstm1 gate partials ----------
        {
            const float* Sv = g_S1v[rd];
            float acc[8];
#pragma unroll
            for (int a = 0; a < 8; a++) acc[a] = 0.f;
            int base = (ks * 12) * 256 + b * 4;
#pragma unroll
            for (int i = 0; i < 12; i++) {
                float4 s4 = __ldcg((const float4*)(Sv + base + i * 256));
                int kk = (ks * 12 + i) * 4;
#pragma unroll
                for (int r = 0; r < 4; r++) {
                    float sr = (r == 0) ? s4.x : (r == 1) ? s4.y : (r == 2) ? s4.z : s4.w;
                    const float* wp = sW1v + (size_t)(kk + r) * 8;
                    float4 wA = *(const float4*)wp;
                    float4 wB = *(const float4*)(wp + 4);
                    acc[0] = fmaf(wA.x, sr, acc[0]); acc[1] = fmaf(wA.y, sr, acc[1]);
                    acc[2] = fmaf(wA.z, sr, acc[2]); acc[3] = fmaf(wA.w, sr, acc[3]);
                    acc[4] = fmaf(wB.x, sr, acc[4]); acc[5] = fmaf(wB.y, sr, acc[5]);
                    acc[6] = fmaf(wB.z, sr, acc[6]); acc[7] = fmaf(wB.w, sr, acc[7]);
                }
            }
#pragma unroll
            for (int a = 0; a < 8; a++) sP[ks * 512 + a * 64 + b] = acc[a];
        }
        __syncthreads();
        {   // combine + embedding-gate gather: 512 threads cover 8 a x 64 b
            int a = tid >> 6, b2 = tid & 63;
            int c = (a >> 1) * 256 + bid * 2 + (a & 1);
            int row = text[b2 * 256 + t] & 4095;
            float s = g_EW[(size_t)row * 1024 + c];
#pragma unroll
            for (int k2 = 0; k2 < 8; k2++) s += sP[k2 * 512 + a * 64 + b2];
            sG[a * 64 + b2] = s;
        }
        __syncthreads();
        if (tid < 128) {
            int jl = tid >> 6, b2 = tid & 63;
            int j = bid * 2 + jl;
            float gi = sG[(0 + jl) * 64 + b2], gf = sG[(2 + jl) * 64 + b2];
            float gg = sG[(4 + jl) * 64 + b2], go = sG[(6 + jl) * 64 + b2];
            float cn = sigm(gf) * g_c1[j * 64 + b2] + sigm(gi) * tanhf(gg);
            float hn = sigm(go) * tanhf(cn);
            g_c1[j * 64 + b2] = cn;
            int k1 = 128 + j;
            g_S1v[wr][(k1 >> 2) * 256 + b2 * 4 + (k1 & 3)] = hn;   // h1(t) for P1(t+1)
            g_S2v[rd][(j >> 2) * 256 + b2 * 4 + (j & 3)] = hn;     // h1(t) for P2(t)
        }
        gbar(++ep);
        // ---------- P2: lstm2 ----------
        {
            const float* Sv = g_S2v[rd];
            float acc[4] = {0.f, 0.f, 0.f, 0.f};
            int base = (ks * 12) * 256 + b * 4;
#pragma unroll
            for (int i = 0; i < 12; i++) {
                float4 s4 = __ldcg((const float4*)(Sv + base + i * 256));
                int kk = (ks * 12 + i) * 4;
#pragma unroll
                for (int r = 0; r < 4; r++) {
                    float sr = (r == 0) ? s4.x : (r == 1) ? s4.y : (r == 2) ? s4.z : s4.w;
                    float4 w = *(const float4*)(sW2v + (size_t)(kk + r) * 4);
                    acc[0] = fmaf(w.x, sr, acc[0]); acc[1] = fmaf(w.y, sr, acc[1]);
                    acc[2] = fmaf(w.z, sr, acc[2]); acc[3] = fmaf(w.w, sr, acc[3]);
                }
            }
#pragma unroll
            for (int q = 0; q < 4; q++) sP[ks * 512 + q * 64 + b] = acc[q];
        }
        __syncthreads();
        if (tid < 256) {
            int q = tid >> 6, b2 = tid & 63;
            float s = sB2[q];
#pragma unroll
            for (int k2 = 0; k2 < 8; k2++) s += sP[k2 * 512 + q * 64 + b2];
            sG[q * 64 + b2] = s;
        }
        __syncthreads();
        if (tid < 64) {
            int b2 = tid;
            float gi = sG[0 * 64 + b2], gf = sG[1 * 64 + b2];
            float gg = sG[2 * 64 + b2], go = sG[3 * 64 + b2];
            float cn = sigm(gf) * g_c2[bid * 64 + b2] + sigm(gi) * tanhf(gg);
            float hn = sigm(go) * tanhf(cn);
            g_c2[bid * 64 + b2] = cn;
            int k2i = 256 + bid;
            g_S2v[wr][(k2i >> 2) * 256 + b2 * 4 + (k2i & 3)] = hn;  // h2(t)
            g_AllT[(size_t)t * 16384 + bid * 64 + b2] = hn;
        }
        gbar(++ep);
        // ---------- P3: attention (blocks 0..63, one batch row each) ----------
        if (bid < 64) {
            const int b3 = bid;
            if (tid < 128) {
                int k = 256 + tid;
                sH2f[tid] = __ldcg(&g_S2v[wr][(k >> 2) * 256 + b3 * 4 + (k & 3)]);
            }
            __syncthreads();
            // energies: 8 lanes per row, fully coalesced
            {
                const float4* sH2v4 = (const float4*)sH2f;
                int ch = lane & 7, rsub = lane >> 3;
                float4 h0 = sH2v4[ch], h1v = sH2v4[ch + 8], h2v = sH2v4[ch + 16], h3v = sH2v4[ch + 24];
                const float4* kbase = (const float4*)(key + (size_t)b3 * 512 * 128);
#pragma unroll
                for (int j = 0; j < 8; j++) {
                    int row = wrp * 32 + j * 4 + rsub;
                    const float4* kp = kbase + (size_t)row * 32;
                    float4 k0 = __ldg(kp + ch), k1 = __ldg(kp + ch + 8);
                    float4 k2 = __ldg(kp + ch + 16), k3 = __ldg(kp + ch + 24);
                    float e = k0.x * h0.x;
                    e = fmaf(k0.y, h0.y, e); e = fmaf(k0.z, h0.z, e); e = fmaf(k0.w, h0.w, e);
                    e = fmaf(k1.x, h1v.x, e); e = fmaf(k1.y, h1v.y, e); e = fmaf(k1.z, h1v.z, e); e = fmaf(k1.w, h1v.w, e);
                    e = fmaf(k2.x, h2v.x, e); e = fmaf(k2.y, h2v.y, e); e = fmaf(k2.z, h2v.z, e); e = fmaf(k2.w, h2v.w, e);
                    e = fmaf(k3.x, h3v.x, e); e = fmaf(k3.y, h3v.y, e); e = fmaf(k3.z, h3v.z, e); e = fmaf(k3.w, h3v.w, e);
                    e += __shfl_xor_sync(0xffffffffu, e, 4);
                    e += __shfl_xor_sync(0xffffffffu, e, 2);
                    e += __shfl_xor_sync(0xffffffffu, e, 1);
                    if (ch == 0) sEn[row] = e;
                }
            }
            __syncthreads();
            // softmax over 512
            float e = sEn[tid];
            float m = e;
#pragma unroll
            for (int off = 16; off > 0; off >>= 1) m = fmaxf(m, __shfl_xor_sync(0xffffffffu, m, off));
            if (lane == 0) sRed[wrp] = m;
            __syncthreads();
            if (tid < 32) {
                float mm = (tid < 16) ? sRed[tid] : -3.402823466e38f;
#pragma unroll
                for (int off = 8; off > 0; off >>= 1) mm = fmaxf(mm, __shfl_xor_sync(0xffffffffu, mm, off));
                if (tid == 0) sRed[16] = mm;
            }
            __syncthreads();
            float mx = sRed[16];
            float ex = __expf(e - mx);
            sEn[tid] = ex;
            float ssum = ex;
#pragma unroll
            for (int off = 16; off > 0; off >>= 1) ssum += __shfl_xor_sync(0xffffffffu, ssum, off);
            if (lane == 0) sRed[wrp] = ssum;
            __syncthreads();
            if (tid < 32) {
                float tt = (tid < 16) ? sRed[tid] : 0.f;
#pragma unroll
                for (int off = 8; off > 0; off >>= 1) tt += __shfl_xor_sync(0xffffffffu, tt, off);
                if (tid == 0) sRed[17] = tt;
            }
            __syncthreads();
            // weighted values: 32 float4-cols x 16 tp-groups
            {
                int v4 = tid & 31, g = tid >> 5;
                const float* vb = values + (size_t)b3 * 65536 + v4 * 4;
                float4 a4 = make_float4(0.f, 0.f, 0.f, 0.f);
#pragma unroll 8
                for (int i = 0; i < 32; i++) {
                    int tp = g * 32 + i;
                    float wgt = sEn[tp];
                    float4 vv = __ldg((const float4*)(vb + (size_t)tp * 128));
                    a4.x = fmaf(wgt, vv.x, a4.x); a4.y = fmaf(wgt, vv.y, a4.y);
                    a4.z = fmaf(wgt, vv.z, a4.z); a4.w = fmaf(wgt, vv.w, a4.w);
                }
                ((float4*)(sVal + g * 128))[v4] = a4;
            }
            __syncthreads();
            if (tid < 128) {
                float s = 0.f;
#pragma unroll
                for (int g2 = 0; g2 < 16; g2++) s += sVal[g2 * 128 + tid];
                float cv = s / sRed[17];
                g_S1v[wr][(tid >> 2) * 256 + b3 * 4 + (tid & 3)] = cv;     // ctx(t)
                g_AllT[(size_t)t * 16384 + (128 + tid) * 64 + b3] = cv;
            }
        }
        gbar(++ep);
    }
}

// ------------------------- kernel 3: logits = AllT^T @ E^T + b_out -------------------------
__global__ void __launch_bounds__(256) logits_k(const float* __restrict__ E,
                                                const float* __restrict__ b_out,
                                                float* __restrict__ out) {
    __shared__ __align__(16) float sX[8 * 64];    // [k][b]
    __shared__ __align__(16) float sE[8 * 128];   // [k][v]
    const int v0 = blockIdx.x * 128;
    const int t = blockIdx.y;
    const int tid = threadIdx.x;
    const int vx = tid & 15, bx = tid >> 4;       // v-frags at vx*4 and 64+vx*4; b-frag bx*4
    float4 acc[4][2];
#pragma unroll
    for (int i = 0; i < 4; i++) { acc[i][0] = make_float4(0, 0, 0, 0); acc[i][1] = make_float4(0, 0, 0, 0); }

    const int vl = tid >> 1, cq = tid & 1;
    const int cl = tid >> 4, bq = tid & 15;

    for (int c0 = 0; c0 < 256; c0 += 8) {
        float4 xv4, ev;
        if (tid < 128) xv4 = *(const float4*)(g_AllT + (size_t)t * 16384 + (size_t)(c0 + cl) * 64 + bq * 4);
        ev = *(const float4*)(E + (size_t)(v0 + vl) * 256 + c0 + cq * 4);
        __syncthreads();
        if (tid < 128) *(float4*)&sX[cl * 64 + bq * 4] = xv4;
        sE[(cq * 4 + 0) * 128 + vl] = ev.x;
        sE[(cq * 4 + 1) * 128 + vl] = ev.y;
        sE[(cq * 4 + 2) * 128 + vl] = ev.z;
        sE[(cq * 4 + 3) * 128 + vl] = ev.w;
        __syncthreads();
#pragma unroll
        for (int k = 0; k < 8; k++) {
            float4 xb = *(const float4*)&sX[k * 64 + bx * 4];
            float4 e0 = *(const float4*)&sE[k * 128 + vx * 4];
            float4 e1 = *(const float4*)&sE[k * 128 + 64 + vx * 4];
            float xs[4] = {xb.x, xb.y, xb.z, xb.w};
#pragma unroll
            for (int bb = 0; bb < 4; bb++) {
                acc[bb][0].x = fmaf(xs[bb], e0.x, acc[bb][0].x);
                acc[bb][0].y = fmaf(xs[bb], e0.y, acc[bb][0].y);
                acc[bb][0].z = fmaf(xs[bb], e0.z, acc[bb][0].z);
                acc[bb][0].w = fmaf(xs[bb], e0.w, acc[bb][0].w);
                acc[bb][1].x = fmaf(xs[bb], e1.x, acc[bb][1].x);
                acc[bb][1].y = fmaf(xs[bb], e1.y, acc[bb][1].y);
                acc[bb][1].z = fmaf(xs[bb], e1.z, acc[bb][1].z);
                acc[bb][1].w = fmaf(xs[bb], e1.w, acc[bb][1].w);
            }
        }
        __syncthreads();
    }
    float4 bo0 = *(const float4*)(b_out + v0 + vx * 4);
    float4 bo1 = *(const float4*)(b_out + v0 + 64 + vx * 4);
#pragma unroll
    for (int bb = 0; bb < 4; bb++) {
        int row = (bx * 4 + bb) * 256 + t;
        float* op = out + (size_t)row * 4096 + v0;
        float4 r0 = make_float4(acc[bb][0].x + bo0.x, acc[bb][0].y + bo0.y,
                                acc[bb][0].z + bo0.z, acc[bb][0].w + bo0.w);
        float4 r1 = make_float4(acc[bb][1].x + bo1.x, acc[bb][1].y + bo1.y,
                                acc[bb][1].z + bo1.z, acc[bb][1].w + bo1.w);
        *(float4*)(op + vx * 4) = r0;
        *(float4*)(op + 64 + vx * 4) = r1;
    }
}

// ------------------------- launch -------------------------
extern "C" void kernel_launch(void* const* d_in, const int* in_sizes, int n_in,
                              void* d_out, int out_size) {
    (void)in_sizes; (void)n_in; (void)out_size;
    const float* key    = (const float*)d_in[0];
    const float* values = (const float*)d_in[1];
    const int*   text   = (const int*)d_in[3];
    const float* E      = (const float*)d_in[4];
    const float* W_ih1  = (const float*)d_in[5];
    const float* W_hh1  = (const float*)d_in[6];
    const float* b_ih1  = (const float*)d_in[7];
    const float* b_hh1  = (const float*)d_in[8];
    const float* W_ih2  = (const float*)d_in[9];
    const float* W_hh2  = (const float*)d_in[10];
    const float* b_ih2  = (const float*)d_in[11];
    const float* b_hh2  = (const float*)d_in[12];
    const float* b_out  = (const float*)d_in[13];
    float*       out    = (float*)d_out;

    prep_k<<<128, 256>>>();
    ew_k<<<dim3(16, 64), 256>>>(E, W_ih1, b_ih1, b_hh1);
    recur_k<<<NBLK, NTHR>>>(key, values, text, W_ih1, W_hh1, W_ih2, W_hh2, b_ih2, b_hh2);
    logits_k<<<dim3(32, 256), 256>>>(E, b_out, out);
}

// round 6
// speedup vs baseline: 1.7723x; 1.0849x over previous
#include <cuda_runtime.h>
#include <cstdint>
#include <cstddef>
#include <math.h>

#define NBLK 128
#define NTHR 512

// ------------------------- device scratch (static, no allocs) -------------------------
__device__ float    g_EW[4096u * 1024u];        // [row][c]: E@W_ih1[:, :256]^T + b_ih1 + b_hh1
__device__ float    g_Gpre[256u * 1024u * 64u]; // [t][c][b]: gate bias from embedding (gathered once)
__device__ float    g_AllT[256u * 256u * 64u];  // [t][c][b], c<128 h2, c>=128 ctx
__device__ float    g_ET[256u * 4096u];         // E transposed: [c][v]
// state, k-major packed in float4 groups: idx(k,b) = (k>>2)*256 + b*4 + (k&3)
__device__ float    g_S1v[2][96 * 256];         // lstm1 input: k<128 ctx, k in [128,384) h1
__device__ float    g_S2v[2][96 * 256];         // lstm2 input: k<256 h1, k in [256,384) h2
__device__ float    g_c1[256 * 64];
__device__ float    g_c2[128 * 64];
__device__ unsigned g_slots[NBLK];

__device__ __forceinline__ float sigm(float x) { return 1.0f / (1.0f + expf(-x)); }

// Atomic-free grid barrier: block i release-stores epoch to slot i; all blocks
// poll the whole slot vector (128 threads, 1 word each) until min >= epoch.
__device__ __forceinline__ void gbar(unsigned epoch) {
    __syncthreads();
    if (threadIdx.x == 0) {
        asm volatile("st.release.gpu.u32 [%0], %1;"
                     :: "l"(&g_slots[blockIdx.x]), "r"(epoch) : "memory");
    }
    bool ok;
    do {
        unsigned v = epoch;
        if (threadIdx.x < NBLK)
            asm volatile("ld.acquire.gpu.u32 %0, [%1];"
                         : "=r"(v) : "l"(&g_slots[threadIdx.x]) : "memory");
        ok = (v >= epoch);
    } while (!__syncthreads_and((int)ok));
}

// ------------------------- kernel 0: zero recurrent state -------------------------
__global__ void prep_k() {
    int i0 = blockIdx.x * blockDim.x + threadIdx.x;
    int st = gridDim.x * blockDim.x;
    for (int i = i0; i < 96 * 256; i += st) { g_S1v[0][i] = 0.f; g_S2v[0][i] = 0.f; }
    for (int i = i0; i < 256 * 64; i += st) g_c1[i] = 0.f;
    for (int i = i0; i < 128 * 64; i += st) g_c2[i] = 0.f;
    if (i0 < NBLK) g_slots[i0] = 0u;
}

// ------------------------- kernel 1: EW[v][c] = E[v,:] . W_ih1[c, :256] + bias -------------------------
__global__ void __launch_bounds__(256) ew_k(const float* __restrict__ E,
                                            const float* __restrict__ W_ih1,
                                            const float* __restrict__ b_ih1,
                                            const float* __restrict__ b_hh1) {
    __shared__ __align__(16) float sA[16][68];   // [k][v]
    __shared__ __align__(16) float sB[16][68];   // [k][c]
    const int c0 = blockIdx.x * 64, v0 = blockIdx.y * 64;
    const int tid = threadIdx.x;
    const int lw = tid >> 2, kq = tid & 3;
    const int cx = tid & 15, vxx = tid >> 4;
    float4 acc[4];
    acc[0] = acc[1] = acc[2] = acc[3] = make_float4(0, 0, 0, 0);
    for (int k0 = 0; k0 < 256; k0 += 16) {
        float4 av = *(const float4*)(E + (size_t)(v0 + lw) * 256 + k0 + kq * 4);
        float4 bv = *(const float4*)(W_ih1 + (size_t)(c0 + lw) * 384 + k0 + kq * 4);
        __syncthreads();
        sA[kq * 4 + 0][lw] = av.x; sA[kq * 4 + 1][lw] = av.y;
        sA[kq * 4 + 2][lw] = av.z; sA[kq * 4 + 3][lw] = av.w;
        sB[kq * 4 + 0][lw] = bv.x; sB[kq * 4 + 1][lw] = bv.y;
        sB[kq * 4 + 2][lw] = bv.z; sB[kq * 4 + 3][lw] = bv.w;
        __syncthreads();
#pragma unroll
        for (int k = 0; k < 16; k++) {
            float4 cv = *(const float4*)&sB[k][cx * 4];
            float4 vv = *(const float4*)&sA[k][vxx * 4];
            float vs[4] = {vv.x, vv.y, vv.z, vv.w};
#pragma unroll
            for (int vi = 0; vi < 4; vi++) {
                acc[vi].x = fmaf(vs[vi], cv.x, acc[vi].x);
                acc[vi].y = fmaf(vs[vi], cv.y, acc[vi].y);
                acc[vi].z = fmaf(vs[vi], cv.z, acc[vi].z);
                acc[vi].w = fmaf(vs[vi], cv.w, acc[vi].w);
            }
        }
    }
    float4 bi = *(const float4*)(b_ih1 + c0 + cx * 4);
    float4 bh = *(const float4*)(b_hh1 + c0 + cx * 4);
    float4 bias = make_float4(bi.x + bh.x, bi.y + bh.y, bi.z + bh.z, bi.w + bh.w);
#pragma unroll
    for (int vi = 0; vi < 4; vi++) {
        float4 r = make_float4(acc[vi].x + bias.x, acc[vi].y + bias.y,
                               acc[vi].z + bias.z, acc[vi].w + bias.w);
        *(float4*)(g_EW + (size_t)(v0 + vxx * 4 + vi) * 1024 + c0 + cx * 4) = r;
    }
}

// ------------------------- kernel 1b: Gpre[t][c][b] = EW[text[b][t]][c] -------------------------
__global__ void __launch_bounds__(512) gpre_k(const int* __restrict__ text) {
    const int t = blockIdx.x;
    const int tid = threadIdx.x;
    const int b = tid & 63, cs = tid >> 6;   // 8 c-stripes x 64 b
    const int row = text[b * 256 + t] & 4095;
    const float* src = g_EW + (size_t)row * 1024;
    float* dst = g_Gpre + (size_t)t * 65536;
    for (int c = cs; c < 1024; c += 8)
        dst[c * 64 + b] = src[c];
}

// ------------------------- kernel 1c: ET[c][v] = E[v][c] -------------------------
__global__ void __launch_bounds__(256) et_k(const float* __restrict__ E) {
    __shared__ float sT[32][33];
    const int v0 = blockIdx.x * 32, c0 = blockIdx.y * 32;
    const int tx = threadIdx.x & 31, ty = threadIdx.x >> 5;
#pragma unroll
    for (int i = 0; i < 4; i++)
        sT[ty + i * 8][tx] = E[(size_t)(v0 + ty + i * 8) * 256 + c0 + tx];
    __syncthreads();
#pragma unroll
    for (int i = 0; i < 4; i++)
        g_ET[(size_t)(c0 + ty + i * 8) * 4096 + v0 + tx] = sT[tx][ty + i * 8];
}

// ------------------------- kernel 2: persistent recurrence -------------------------
__global__ void __launch_bounds__(NTHR, 1) recur_k(
    const float* __restrict__ key, const float* __restrict__ values,
    const float* __restrict__ W_ih1, const float* __restrict__ W_hh1,
    const float* __restrict__ W_ih2, const float* __restrict__ W_hh2,
    const float* __restrict__ b_ih2, const float* __restrict__ b_hh2) {
    __shared__ __align__(16) float sW1v[384 * 8];   // [k][a], a = gate*2 + jl
    __shared__ __align__(16) float sW2v[384 * 4];   // [k][q], q = gate
    __shared__ __align__(16) float sP[8 * 8 * 64];  // [ks][a][b]
    __shared__ float sG[8 * 64];
    __shared__ float sB2[4];
    __shared__ __align__(16) float sH2f[128];
    __shared__ float sEn[512];
    __shared__ float sRed[32];
    __shared__ __align__(16) float sVal[16 * 128];

    const int tid = threadIdx.x;
    const int bid = blockIdx.x;
    const int b = tid & 63, ks = tid >> 6;   // 8 k-splits x 64 batch
    const int lane = tid & 31, wrp = tid >> 5;

    // weight staging (k-major)
    for (int i = tid; i < 384 * 8; i += NTHR) {
        int k = i >> 3, a = i & 7;
        int c = (a >> 1) * 256 + bid * 2 + (a & 1);
        sW1v[i] = (k < 128) ? W_ih1[(size_t)c * 384 + 256 + k]
                            : W_hh1[(size_t)c * 256 + (k - 128)];
    }
    for (int i = tid; i < 384 * 4; i += NTHR) {
        int k = i >> 2, q = i & 3;
        int c2 = q * 128 + bid;
        sW2v[i] = (k < 256) ? W_ih2[(size_t)c2 * 256 + k]
                            : W_hh2[(size_t)c2 * 128 + (k - 256)];
    }
    if (tid < 4) sB2[tid] = b_ih2[tid * 128 + bid] + b_hh2[tid * 128 + bid];
    __syncthreads();

    unsigned ep = 0;
    for (int t = 0; t < 256; ++t) {
        const int rd = t & 1, wr = rd ^ 1;
        // ---------- P1: lstm1 gate partials ----------
        {
            const float* Sv = g_S1v[rd];
            float acc[8];
#pragma unroll
            for (int a = 0; a < 8; a++) acc[a] = 0.f;
            int base = (ks * 12) * 256 + b * 4;
#pragma unroll
            for (int i = 0; i < 12; i++) {
                float4 s4 = __ldcg((const float4*)(Sv + base + i * 256));
                int kk = (ks * 12 + i) * 4;
#pragma unroll
                for (int r = 0; r < 4; r++) {
                    float sr = (r == 0) ? s4.x : (r == 1) ? s4.y : (r == 2) ? s4.z : s4.w;
                    const float* wp = sW1v + (size_t)(kk + r) * 8;
                    float4 wA = *(const float4*)wp;
                    float4 wB = *(const float4*)(wp + 4);
                    acc[0] = fmaf(wA.x, sr, acc[0]); acc[1] = fmaf(wA.y, sr, acc[1]);
                    acc[2] = fmaf(wA.z, sr, acc[2]); acc[3] = fmaf(wA.w, sr, acc[3]);
                    acc[4] = fmaf(wB.x, sr, acc[4]); acc[5] = fmaf(wB.y, sr, acc[5]);
                    acc[6] = fmaf(wB.z, sr, acc[6]); acc[7] = fmaf(wB.w, sr, acc[7]);
                }
            }
#pragma unroll
            for (int a = 0; a < 8; a++) sP[ks * 512 + a * 64 + b] = acc[a];
        }
        __syncthreads();
        {   // combine + precomputed embedding-gate read (coalesced)
            int a = tid >> 6, b2 = tid & 63;
            int c = (a >> 1) * 256 + bid * 2 + (a & 1);
            float s = __ldcg(&g_Gpre[(size_t)t * 65536 + c * 64 + b2]);
#pragma unroll
            for (int k2 = 0; k2 < 8; k2++) s += sP[k2 * 512 + a * 64 + b2];
            sG[a * 64 + b2] = s;
        }
        __syncthreads();
        if (tid < 128) {
            int jl = tid >> 6, b2 = tid & 63;
            int j = bid * 2 + jl;
            float gi = sG[(0 + jl) * 64 + b2], gf = sG[(2 + jl) * 64 + b2];
            float gg = sG[(4 + jl) * 64 + b2], go = sG[(6 + jl) * 64 + b2];
            float cn = sigm(gf) * g_c1[j * 64 + b2] + sigm(gi) * tanhf(gg);
            float hn = sigm(go) * tanhf(cn);
            g_c1[j * 64 + b2] = cn;
            int k1 = 128 + j;
            g_S1v[wr][(k1 >> 2) * 256 + b2 * 4 + (k1 & 3)] = hn;   // h1(t) for P1(t+1)
            g_S2v[rd][(j >> 2) * 256 + b2 * 4 + (j & 3)] = hn;     // h1(t) for P2(t)
        }
        gbar(++ep);
        // ---------- P2: lstm2 ----------
        {
            const float* Sv = g_S2v[rd];
            float acc[4] = {0.f, 0.f, 0.f, 0.f};
            int base = (ks * 12) * 256 + b * 4;
#pragma unroll
            for (int i = 0; i < 12; i++) {
                float4 s4 = __ldcg((const float4*)(Sv + base + i * 256));
                int kk = (ks * 12 + i) * 4;
#pragma unroll
                for (int r = 0; r < 4; r++) {
                    float sr = (r == 0) ? s4.x : (r == 1) ? s4.y : (r == 2) ? s4.z : s4.w;
                    float4 w = *(const float4*)(sW2v + (size_t)(kk + r) * 4);
                    acc[0] = fmaf(w.x, sr, acc[0]); acc[1] = fmaf(w.y, sr, acc[1]);
                    acc[2] = fmaf(w.z, sr, acc[2]); acc[3] = fmaf(w.w, sr, acc[3]);
                }
            }
#pragma unroll
            for (int q = 0; q < 4; q++) sP[ks * 512 + q * 64 + b] = acc[q];
        }
        __syncthreads();
        if (tid < 256) {
            int q = tid >> 6, b2 = tid & 63;
            float s = sB2[q];
#pragma unroll
            for (int k2 = 0; k2 < 8; k2++) s += sP[k2 * 512 + q * 64 + b2];
            sG[q * 64 + b2] = s;
        }
        __syncthreads();
        if (tid < 64) {
            int b2 = tid;
            float gi = sG[0 * 64 + b2], gf = sG[1 * 64 + b2];
            float gg = sG[2 * 64 + b2], go = sG[3 * 64 + b2];
            float cn = sigm(gf) * g_c2[bid * 64 + b2] + sigm(gi) * tanhf(gg);
            float hn = sigm(go) * tanhf(cn);
            g_c2[bid * 64 + b2] = cn;
            int k2i = 256 + bid;
            g_S2v[wr][(k2i >> 2) * 256 + b2 * 4 + (k2i & 3)] = hn;  // h2(t)
            g_AllT[(size_t)t * 16384 + bid * 64 + b2] = hn;
        }
        gbar(++ep);
        // ---------- P3: attention (blocks 0..63, one batch row each) ----------
        if (bid < 64) {
            const int b3 = bid;
            if (tid < 128) {
                int k = 256 + tid;
                sH2f[tid] = __ldcg(&g_S2v[wr][(k >> 2) * 256 + b3 * 4 + (k & 3)]);
            }
            __syncthreads();
            // energies: 8 lanes per row, fully coalesced
            {
                const float4* sH2v4 = (const float4*)sH2f;
                int ch = lane & 7, rsub = lane >> 3;
                float4 h0 = sH2v4[ch], h1v = sH2v4[ch + 8], h2v = sH2v4[ch + 16], h3v = sH2v4[ch + 24];
                const float4* kbase = (const float4*)(key + (size_t)b3 * 512 * 128);
#pragma unroll
                for (int j = 0; j < 8; j++) {
                    int row = wrp * 32 + j * 4 + rsub;
                    const float4* kp = kbase + (size_t)row * 32;
                    float4 k0 = __ldg(kp + ch), k1 = __ldg(kp + ch + 8);
                    float4 k2 = __ldg(kp + ch + 16), k3 = __ldg(kp + ch + 24);
                    float e = k0.x * h0.x;
                    e = fmaf(k0.y, h0.y, e); e = fmaf(k0.z, h0.z, e); e = fmaf(k0.w, h0.w, e);
                    e = fmaf(k1.x, h1v.x, e); e = fmaf(k1.y, h1v.y, e); e = fmaf(k1.z, h1v.z, e); e = fmaf(k1.w, h1v.w, e);
                    e = fmaf(k2.x, h2v.x, e); e = fmaf(k2.y, h2v.y, e); e = fmaf(k2.z, h2v.z, e); e = fmaf(k2.w, h2v.w, e);
                    e = fmaf(k3.x, h3v.x, e); e = fmaf(k3.y, h3v.y, e); e = fmaf(k3.z, h3v.z, e); e = fmaf(k3.w, h3v.w, e);
                    e += __shfl_xor_sync(0xffffffffu, e, 4);
                    e += __shfl_xor_sync(0xffffffffu, e, 2);
                    e += __shfl_xor_sync(0xffffffffu, e, 1);
                    if (ch == 0) sEn[row] = e;
                }
            }
            __syncthreads();
            // softmax over 512
            float e = sEn[tid];
            float m = e;
#pragma unroll
            for (int off = 16; off > 0; off >>= 1) m = fmaxf(m, __shfl_xor_sync(0xffffffffu, m, off));
            if (lane == 0) sRed[wrp] = m;
            __syncthreads();
            if (tid < 32) {
                float mm = (tid < 16) ? sRed[tid] : -3.402823466e38f;
#pragma unroll
                for (int off = 8; off > 0; off >>= 1) mm = fmaxf(mm, __shfl_xor_sync(0xffffffffu, mm, off));
                if (tid == 0) sRed[16] = mm;
            }
            __syncthreads();
            float mx = sRed[16];
            float ex = __expf(e - mx);
            sEn[tid] = ex;
            float ssum = ex;
#pragma unroll
            for (int off = 16; off > 0; off >>= 1) ssum += __shfl_xor_sync(0xffffffffu, ssum, off);
            if (lane == 0) sRed[wrp] = ssum;
            __syncthreads();
            if (tid < 32) {
                float tt = (tid < 16) ? sRed[tid] : 0.f;
#pragma unroll
                for (int off = 8; off > 0; off >>= 1) tt += __shfl_xor_sync(0xffffffffu, tt, off);
                if (tid == 0) sRed[17] = tt;
            }
            __syncthreads();
            // weighted values: 32 float4-cols x 16 tp-groups
            {
                int v4 = tid & 31, g = tid >> 5;
                const float* vb = values + (size_t)b3 * 65536 + v4 * 4;
                float4 a4 = make_float4(0.f, 0.f, 0.f, 0.f);
#pragma unroll 8
                for (int i = 0; i < 32; i++) {
                    int tp = g * 32 + i;
                    float wgt = sEn[tp];
                    float4 vv = __ldg((const float4*)(vb + (size_t)tp * 128));
                    a4.x = fmaf(wgt, vv.x, a4.x); a4.y = fmaf(wgt, vv.y, a4.y);
                    a4.z = fmaf(wgt, vv.z, a4.z); a4.w = fmaf(wgt, vv.w, a4.w);
                }
                ((float4*)(sVal + g * 128))[v4] = a4;
            }
            __syncthreads();
            if (tid < 128) {
                float s = 0.f;
#pragma unroll
                for (int g2 = 0; g2 < 16; g2++) s += sVal[g2 * 128 + tid];
                float cv = s / sRed[17];
                g_S1v[wr][(tid >> 2) * 256 + b3 * 4 + (tid & 3)] = cv;     // ctx(t)
                g_AllT[(size_t)t * 16384 + (128 + tid) * 64 + b3] = cv;
            }
        }
        gbar(++ep);
    }
}

// ------------------------- kernel 3: logits = AllT^T @ ET + b_out -------------------------
// block tile: 64 b x 128 v per t; 256 threads = 8 warps; warp w -> b rows w*8..w*8+7;
// lane vx=tid&31 -> v frag vx*4. Per-thread acc: 8 b x 4 v.
__global__ void __launch_bounds__(256) logits_k(const float* __restrict__ b_out,
                                                float* __restrict__ out) {
    __shared__ __align__(16) float sX[16 * 64];    // [k][b]
    __shared__ __align__(16) float sE[16 * 128];   // [k][v]
    const int v0 = blockIdx.x * 128;
    const int t = blockIdx.y;
    const int tid = threadIdx.x;
    const int vx = tid & 31, bx = tid >> 5;
    float4 acc[8];
#pragma unroll
    for (int i = 0; i < 8; i++) acc[i] = make_float4(0, 0, 0, 0);

    const int kl = tid >> 4, bq = tid & 15;   // sX loader (256 f4)
    const int ke = tid >> 5, ve = tid & 31;   // sE loader (2 f4 per thread)

    for (int c0 = 0; c0 < 256; c0 += 16) {
        float4 xv = *(const float4*)(g_AllT + (size_t)t * 16384 + (size_t)(c0 + kl) * 64 + bq * 4);
        float4 e0 = *(const float4*)(g_ET + (size_t)(c0 + ke) * 4096 + v0 + ve * 4);
        float4 e1 = *(const float4*)(g_ET + (size_t)(c0 + ke + 8) * 4096 + v0 + ve * 4);
        __syncthreads();
        *(float4*)&sX[kl * 64 + bq * 4] = xv;
        *(float4*)&sE[ke * 128 + ve * 4] = e0;
        *(float4*)&sE[(ke + 8) * 128 + ve * 4] = e1;
        __syncthreads();
#pragma unroll
        for (int k = 0; k < 16; k++) {
            float4 ev = *(const float4*)&sE[k * 128 + vx * 4];
            float4 x0 = *(const float4*)&sX[k * 64 + bx * 8];
            float4 x1 = *(const float4*)&sX[k * 64 + bx * 8 + 4];
            float xs[8] = {x0.x, x0.y, x0.z, x0.w, x1.x, x1.y, x1.z, x1.w};
#pragma unroll
            for (int j = 0; j < 8; j++) {
                acc[j].x = fmaf(xs[j], ev.x, acc[j].x);
                acc[j].y = fmaf(xs[j], ev.y, acc[j].y);
                acc[j].z = fmaf(xs[j], ev.z, acc[j].z);
                acc[j].w = fmaf(xs[j], ev.w, acc[j].w);
            }
        }
    }
    float4 bo = *(const float4*)(b_out + v0 + vx * 4);
#pragma unroll
    for (int j = 0; j < 8; j++) {
        int bb = bx * 8 + j;
        float4 r = make_float4(acc[j].x + bo.x, acc[j].y + bo.y,
                               acc[j].z + bo.z, acc[j].w + bo.w);
        *(float4*)(out + ((size_t)bb * 256 + t) * 4096 + v0 + vx * 4) = r;
    }
}

// ------------------------- launch -------------------------
extern "C" void kernel_launch(void* const* d_in, const int* in_sizes, int n_in,
                              void* d_out, int out_size) {
    (void)in_sizes; (void)n_in; (void)out_size;
    const float* key    = (const float*)d_in[0];
    const float* values = (const float*)d_in[1];
    const int*   text   = (const int*)d_in[3];
    const float* E      = (const float*)d_in[4];
    const float* W_ih1  = (const float*)d_in[5];
    const float* W_hh1  = (const float*)d_in[6];
    const float* b_ih1  = (const float*)d_in[7];
    const float* b_hh1  = (const float*)d_in[8];
    const float* W_ih2  = (const float*)d_in[9];
    const float* W_hh2  = (const float*)d_in[10];
    const float* b_ih2  = (const float*)d_in[11];
    const float* b_hh2  = (const float*)d_in[12];
    const float* b_out  = (const float*)d_in[13];
    float*       out    = (float*)d_out;

    prep_k<<<128, 256>>>();
    ew_k<<<dim3(16, 64), 256>>>(E, W_ih1, b_ih1, b_hh1);
    gpre_k<<<256, 512>>>(text);
    et_k<<<dim3(128, 8), 256>>>(E);
    recur_k<<<NBLK, NTHR>>>(key, values, W_ih1, W_hh1, W_ih2, W_hh2, b_ih2, b_hh2);
    logits_k<<<dim3(32, 256), 256>>>(b_out, out);
}